// round 1
// baseline (speedup 1.0000x reference)
#include <cuda_runtime.h>
#include <math.h>

#define D_MODEL 1024
#define NHEADS  16
#define DEPTH   64
#define BATCH   2
#define SEQ     2048
#define NROWS   (BATCH * SEQ)   // 4096

// Scratch (allocation-free per harness rules)
__device__ float g_q[NROWS * D_MODEL];
__device__ float g_k[NROWS * D_MODEL];
__device__ float g_v[NROWS * D_MODEL];
__device__ float g_o[NROWS * D_MODEL];

// ---------------------------------------------------------------------------
// GEMM-NT with bias: C[M,N] = A[M,K] @ B[N,K]^T + bias[N]
// (torch Linear: x @ W.T + b, W stored [N,K] row-major)
// Tile: BM=BN=128, BK=8. 256 threads (16x16), each computes 8x8 outputs
// arranged as 2x2 blocks of 4x4 (conflict-free float4 smem reads).
// Requires M%128==0, N%128==0, K%8==0 (true here: 4096/1024/1024).
// ---------------------------------------------------------------------------
__global__ __launch_bounds__(256) void gemm_nt_bias(
    const float* __restrict__ A, const float* __restrict__ B,
    const float* __restrict__ bias, float* __restrict__ C,
    int M, int N, int K)
{
    __shared__ float As[8][128];
    __shared__ float Bs[8][128];

    const int tid = threadIdx.x;
    const int tx  = tid & 15;      // n-direction
    const int ty  = tid >> 4;      // m-direction
    const int m0  = blockIdx.y * 128;
    const int n0  = blockIdx.x * 128;

    float acc[8][8];
#pragma unroll
    for (int i = 0; i < 8; i++)
#pragma unroll
        for (int j = 0; j < 8; j++) acc[i][j] = 0.f;

    const int lrow = tid >> 1;         // 0..127
    const int lcol = (tid & 1) * 4;    // 0 or 4
    const float* Aptr = A + (size_t)(m0 + lrow) * K + lcol;
    const float* Bptr = B + (size_t)(n0 + lrow) * K + lcol;

    for (int k0 = 0; k0 < K; k0 += 8) {
        float4 av = *(const float4*)(Aptr + k0);
        float4 bv = *(const float4*)(Bptr + k0);
        As[lcol + 0][lrow] = av.x;
        As[lcol + 1][lrow] = av.y;
        As[lcol + 2][lrow] = av.z;
        As[lcol + 3][lrow] = av.w;
        Bs[lcol + 0][lrow] = bv.x;
        Bs[lcol + 1][lrow] = bv.y;
        Bs[lcol + 2][lrow] = bv.z;
        Bs[lcol + 3][lrow] = bv.w;
        __syncthreads();

#pragma unroll
        for (int kk = 0; kk < 8; kk++) {
            float4 a0 = *(const float4*)(&As[kk][ty * 4]);
            float4 a1 = *(const float4*)(&As[kk][64 + ty * 4]);
            float4 b0 = *(const float4*)(&Bs[kk][tx * 4]);
            float4 b1 = *(const float4*)(&Bs[kk][64 + tx * 4]);
            float a[8] = {a0.x, a0.y, a0.z, a0.w, a1.x, a1.y, a1.z, a1.w};
            float b[8] = {b0.x, b0.y, b0.z, b0.w, b1.x, b1.y, b1.z, b1.w};
#pragma unroll
            for (int i = 0; i < 8; i++)
#pragma unroll
                for (int j = 0; j < 8; j++)
                    acc[i][j] = fmaf(a[i], b[j], acc[i][j]);
        }
        __syncthreads();
    }

    // Epilogue: row i -> m = ty*4+i (i<4) or 64+ty*4+(i-4); cols same with tx.
#pragma unroll
    for (int i = 0; i < 8; i++) {
        int m = m0 + ((i < 4) ? (ty * 4 + i) : (64 + ty * 4 + (i - 4)));
        float* crow = C + (size_t)m * N;
#pragma unroll
        for (int jb = 0; jb < 2; jb++) {
            int n = n0 + ((jb == 0) ? (tx * 4) : (64 + tx * 4));
            float4 o;
            o.x = acc[i][jb * 4 + 0] + bias[n + 0];
            o.y = acc[i][jb * 4 + 1] + bias[n + 1];
            o.z = acc[i][jb * 4 + 2] + bias[n + 2];
            o.w = acc[i][jb * 4 + 3] + bias[n + 3];
            *(float4*)(crow + n) = o;
        }
    }
}

// ---------------------------------------------------------------------------
// Flash attention (fp32, causal), one thread per query row.
// BM=128 query rows per block, BN=32 keys per tile, depth=64.
// Q/K/V stored [B*S, D_MODEL] with head h at column offset h*64.
// Heavy (high q-index) blocks are launched first for load balance.
// ---------------------------------------------------------------------------
#define FA_BM 128
#define FA_BN 32

__global__ __launch_bounds__(128) void flash_attn(
    const float* __restrict__ Q, const float* __restrict__ K,
    const float* __restrict__ V, float* __restrict__ O)
{
    __shared__ float Ks[FA_BN][DEPTH];
    __shared__ float Vs[FA_BN][DEPTH];

    const int tid = threadIdx.x;
    const int bh  = blockIdx.y;          // 0..31
    const int b   = bh >> 4;
    const int h   = bh & 15;
    const int nqt = SEQ / FA_BM;         // 16
    const int q0  = (nqt - 1 - (int)blockIdx.x) * FA_BM;  // descending: heavy first
    const int srow = q0 + tid;

    const float* qptr = Q + (size_t)(b * SEQ + srow) * D_MODEL + h * DEPTH;
    float4 qr[16];
#pragma unroll
    for (int i = 0; i < 16; i++) qr[i] = *(const float4*)(qptr + i * 4);

    float4 acc[16];
#pragma unroll
    for (int i = 0; i < 16; i++) acc[i] = make_float4(0.f, 0.f, 0.f, 0.f);
    float mrun = -1e30f, lrun = 0.f;

    const float scale = 0.125f;  // 1/sqrt(64)
    const int ntiles = q0 / FA_BN + FA_BM / FA_BN;  // covers keys [0, q0+127]

    for (int t = 0; t < ntiles; t++) {
        const int k0 = t * FA_BN;
        // Load K/V tile: 32x64 floats = 512 float4; 128 threads -> 4 each
#pragma unroll
        for (int i = 0; i < 4; i++) {
            int idx = tid + i * 128;      // 0..511
            int row = idx >> 4;           // 0..31
            int c4  = idx & 15;
            size_t goff = (size_t)(b * SEQ + k0 + row) * D_MODEL + h * DEPTH + c4 * 4;
            *(float4*)(&Ks[row][c4 * 4]) = *(const float4*)(K + goff);
            *(float4*)(&Vs[row][c4 * 4]) = *(const float4*)(V + goff);
        }
        __syncthreads();

        // Scores for this thread's query row vs 32 keys
        float s[FA_BN];
        float tmax = -1e30f;
#pragma unroll
        for (int j = 0; j < FA_BN; j++) {
            float s0 = 0.f, s1 = 0.f, s2 = 0.f, s3 = 0.f;
#pragma unroll
            for (int d4 = 0; d4 < 16; d4++) {
                float4 kv = *(const float4*)(&Ks[j][d4 * 4]);
                s0 = fmaf(qr[d4].x, kv.x, s0);
                s1 = fmaf(qr[d4].y, kv.y, s1);
                s2 = fmaf(qr[d4].z, kv.z, s2);
                s3 = fmaf(qr[d4].w, kv.w, s3);
            }
            float sj = ((s0 + s1) + (s2 + s3)) * scale;
            if (k0 + j > srow) sj = -1e30f;   // causal mask (matches -1e9 additive)
            s[j] = sj;
            tmax = fmaxf(tmax, sj);
        }

        const float mnew = fmaxf(mrun, tmax);
        const float corr = __expf(mrun - mnew);
        lrun *= corr;
#pragma unroll
        for (int i = 0; i < 16; i++) {
            acc[i].x *= corr; acc[i].y *= corr;
            acc[i].z *= corr; acc[i].w *= corr;
        }

#pragma unroll
        for (int j = 0; j < FA_BN; j++) {
            float p = __expf(s[j] - mnew);   // masked -> exp(-1e30 - m) == 0
            lrun += p;
#pragma unroll
            for (int d4 = 0; d4 < 16; d4++) {
                float4 vv = *(const float4*)(&Vs[j][d4 * 4]);
                acc[d4].x = fmaf(p, vv.x, acc[d4].x);
                acc[d4].y = fmaf(p, vv.y, acc[d4].y);
                acc[d4].z = fmaf(p, vv.z, acc[d4].z);
                acc[d4].w = fmaf(p, vv.w, acc[d4].w);
            }
        }
        mrun = mnew;
        __syncthreads();
    }

    const float inv = 1.f / lrun;
    float* optr = O + (size_t)(b * SEQ + srow) * D_MODEL + h * DEPTH;
#pragma unroll
    for (int i = 0; i < 16; i++) {
        float4 o;
        o.x = acc[i].x * inv; o.y = acc[i].y * inv;
        o.z = acc[i].z * inv; o.w = acc[i].w * inv;
        *(float4*)(optr + i * 4) = o;
    }
}

// ---------------------------------------------------------------------------
// Launch
// Inputs (metadata order): 0:v 1:k 2:q 3:mask 4:wq_w 5:wq_b 6:wk_w 7:wk_b
//                          8:wv_w 9:wv_b 10:dense_w 11:dense_b
// ---------------------------------------------------------------------------
extern "C" void kernel_launch(void* const* d_in, const int* in_sizes, int n_in,
                              void* d_out, int out_size)
{
    const float* v       = (const float*)d_in[0];
    const float* k       = (const float*)d_in[1];
    const float* q       = (const float*)d_in[2];
    const float* wq_w    = (const float*)d_in[4];
    const float* wq_b    = (const float*)d_in[5];
    const float* wk_w    = (const float*)d_in[6];
    const float* wk_b    = (const float*)d_in[7];
    const float* wv_w    = (const float*)d_in[8];
    const float* wv_b    = (const float*)d_in[9];
    const float* dense_w = (const float*)d_in[10];
    const float* dense_b = (const float*)d_in[11];
    float* out = (float*)d_out;

    float *gq, *gk, *gv, *go;
    cudaGetSymbolAddress((void**)&gq, g_q);
    cudaGetSymbolAddress((void**)&gk, g_k);
    cudaGetSymbolAddress((void**)&gv, g_v);
    cudaGetSymbolAddress((void**)&go, g_o);

    dim3 gemm_grid(D_MODEL / 128, NROWS / 128);  // (8, 32)
    gemm_nt_bias<<<gemm_grid, 256>>>(q, wq_w, wq_b, gq, NROWS, D_MODEL, D_MODEL);
    gemm_nt_bias<<<gemm_grid, 256>>>(k, wk_w, wk_b, gk, NROWS, D_MODEL, D_MODEL);
    gemm_nt_bias<<<gemm_grid, 256>>>(v, wv_w, wv_b, gv, NROWS, D_MODEL, D_MODEL);

    dim3 fa_grid(SEQ / FA_BM, BATCH * NHEADS);   // (16, 32)
    flash_attn<<<fa_grid, 128>>>(gq, gk, gv, go);

    gemm_nt_bias<<<gemm_grid, 256>>>(go, dense_w, dense_b, out, NROWS, D_MODEL, D_MODEL);
}

// round 3
// speedup vs baseline: 1.2639x; 1.2639x over previous
#include <cuda_runtime.h>
#include <cuda_bf16.h>
#include <cstdint>
#include <math.h>

#define D_MODEL 1024
#define NHEADS  16
#define DEPTH   64
#define BATCH   2
#define SEQ     2048
#define NROWS   (BATCH * SEQ)   // 4096

// ---------------- scratch (no allocation allowed) ----------------
__device__ float g_q[NROWS * D_MODEL];
__device__ float g_k[NROWS * D_MODEL];
__device__ float g_v[NROWS * D_MODEL];
__device__ float g_o[NROWS * D_MODEL];
__device__ __nv_bfloat16 s_ahi[NROWS * D_MODEL];
__device__ __nv_bfloat16 s_alo[NROWS * D_MODEL];
__device__ __nv_bfloat16 s_whi[D_MODEL * D_MODEL];
__device__ __nv_bfloat16 s_wlo[D_MODEL * D_MODEL];

// ---------------- helpers ----------------
__device__ __forceinline__ uint32_t smem_u32(const void* p) {
    uint32_t a;
    asm("{ .reg .u64 t; cvta.to.shared.u64 t, %1; cvt.u32.u64 %0, t; }" : "=r"(a) : "l"(p));
    return a;
}
__device__ __forceinline__ void ldmatrix_x4(uint32_t* r, uint32_t addr) {
    asm volatile("ldmatrix.sync.aligned.m8n8.x4.shared.b16 {%0,%1,%2,%3}, [%4];"
                 : "=r"(r[0]), "=r"(r[1]), "=r"(r[2]), "=r"(r[3]) : "r"(addr));
}
__device__ __forceinline__ void ldmatrix_x2(uint32_t* r, uint32_t addr) {
    asm volatile("ldmatrix.sync.aligned.m8n8.x2.shared.b16 {%0,%1}, [%2];"
                 : "=r"(r[0]), "=r"(r[1]) : "r"(addr));
}
__device__ __forceinline__ void mma_bf16(float* c, const uint32_t* a, const uint32_t* b) {
    asm volatile(
        "mma.sync.aligned.m16n8k16.row.col.f32.bf16.bf16.f32 "
        "{%0,%1,%2,%3}, {%4,%5,%6,%7}, {%8,%9}, {%0,%1,%2,%3};"
        : "+f"(c[0]), "+f"(c[1]), "+f"(c[2]), "+f"(c[3])
        : "r"(a[0]), "r"(a[1]), "r"(a[2]), "r"(a[3]), "r"(b[0]), "r"(b[1]));
}

// ---------------------------------------------------------------------------
// split fp32 -> (hi, lo) bf16 pair:  x = hi + lo + O(2^-18 x)
// ---------------------------------------------------------------------------
__global__ __launch_bounds__(256) void split_bf16(
    const float* __restrict__ x, __nv_bfloat16* __restrict__ hi,
    __nv_bfloat16* __restrict__ lo, int n4)
{
    int i = blockIdx.x * blockDim.x + threadIdx.x;
    if (i >= n4) return;
    float4 v = ((const float4*)x)[i];
    __nv_bfloat16 h0 = __float2bfloat16_rn(v.x);
    __nv_bfloat16 h1 = __float2bfloat16_rn(v.y);
    __nv_bfloat16 h2 = __float2bfloat16_rn(v.z);
    __nv_bfloat16 h3 = __float2bfloat16_rn(v.w);
    __nv_bfloat16 l0 = __float2bfloat16_rn(v.x - __bfloat162float(h0));
    __nv_bfloat16 l1 = __float2bfloat16_rn(v.y - __bfloat162float(h1));
    __nv_bfloat16 l2 = __float2bfloat16_rn(v.z - __bfloat162float(h2));
    __nv_bfloat16 l3 = __float2bfloat16_rn(v.w - __bfloat162float(h3));
    ((__nv_bfloat162*)hi)[2 * i]     = __nv_bfloat162(h0, h1);
    ((__nv_bfloat162*)hi)[2 * i + 1] = __nv_bfloat162(h2, h3);
    ((__nv_bfloat162*)lo)[2 * i]     = __nv_bfloat162(l0, l1);
    ((__nv_bfloat162*)lo)[2 * i + 1] = __nv_bfloat162(l2, l3);
}

// ---------------------------------------------------------------------------
// mma.sync split-bf16 GEMM-NT: C[M,N] = A[M,K] @ W[N,K]^T + bias
// Tile BM=128, BN=64, BK=32. 256 threads = 8 warps (4 m x 2 n), warp 32x32.
// Each warp: 2 m16-tiles x 4 n8-tiles, 3 precision passes (hh, hl, lh).
// smem rows padded to 40 halves (80B) -> conflict-free ldmatrix.
// ---------------------------------------------------------------------------
#define GK 1024
#define GN 1024
#define BKC 32
#define LDS 40   // padded row stride in halves

__global__ __launch_bounds__(256, 2) void gemm_mma_split(
    const __nv_bfloat16* __restrict__ Ahi, const __nv_bfloat16* __restrict__ Alo,
    const __nv_bfloat16* __restrict__ Bhi, const __nv_bfloat16* __restrict__ Blo,
    const float* __restrict__ bias, float* __restrict__ C)
{
    __shared__ __nv_bfloat16 sAhi[128 * LDS];
    __shared__ __nv_bfloat16 sAlo[128 * LDS];
    __shared__ __nv_bfloat16 sBhi[64 * LDS];
    __shared__ __nv_bfloat16 sBlo[64 * LDS];

    const int tid = threadIdx.x;
    const int wid = tid >> 5;
    const int lane = tid & 31;
    const int warp_m = wid & 3;      // 0..3 -> m offset *32
    const int warp_n = wid >> 2;     // 0..1 -> n offset *32
    const int m0 = blockIdx.y * 128;
    const int n0 = blockIdx.x * 64;

    float acc[2][4][4];
#pragma unroll
    for (int i = 0; i < 2; i++)
#pragma unroll
        for (int j = 0; j < 4; j++)
#pragma unroll
            for (int l = 0; l < 4; l++) acc[i][j][l] = 0.f;

    const int arow = tid >> 2;          // 0..63
    const int acol = (tid & 3) * 8;     // halves: 0,8,16,24

    // ldmatrix lane addressing
    const int lr  = lane & 15;                 // A row within 16
    const int lkq = (lane >> 4) * 8;           // A k-quad: 0 or 8
    const int br  = lane & 7;                  // B row within 8
    const int bkq = ((lane >> 3) & 1) * 8;     // B k-quad (lanes 16-31 replicate)

    for (int kc = 0; kc < GK; kc += BKC) {
        // ---- load tiles ----
        const size_t aoff0 = (size_t)(m0 + arow) * GK + kc + acol;
        const size_t aoff1 = (size_t)(m0 + 64 + arow) * GK + kc + acol;
        const size_t boff  = (size_t)(n0 + arow) * GK + kc + acol;
        *(uint4*)&sAhi[arow * LDS + acol]        = *(const uint4*)(Ahi + aoff0);
        *(uint4*)&sAhi[(arow + 64) * LDS + acol] = *(const uint4*)(Ahi + aoff1);
        *(uint4*)&sAlo[arow * LDS + acol]        = *(const uint4*)(Alo + aoff0);
        *(uint4*)&sAlo[(arow + 64) * LDS + acol] = *(const uint4*)(Alo + aoff1);
        *(uint4*)&sBhi[arow * LDS + acol]        = *(const uint4*)(Bhi + boff);
        *(uint4*)&sBlo[arow * LDS + acol]        = *(const uint4*)(Blo + boff);
        __syncthreads();

        // ---- compute ----
#pragma unroll
        for (int ks = 0; ks < 2; ks++) {
            const int kb = ks * 16;
            uint32_t ah[2][4], al[2][4];
#pragma unroll
            for (int mt = 0; mt < 2; mt++) {
                int row = warp_m * 32 + mt * 16 + lr;
                ldmatrix_x4(ah[mt], smem_u32(&sAhi[row * LDS + kb + lkq]));
                ldmatrix_x4(al[mt], smem_u32(&sAlo[row * LDS + kb + lkq]));
            }
            uint32_t bh[4][2], bl[4][2];
#pragma unroll
            for (int nt = 0; nt < 4; nt++) {
                int row = warp_n * 32 + nt * 8 + br;
                ldmatrix_x2(bh[nt], smem_u32(&sBhi[row * LDS + kb + bkq]));
                ldmatrix_x2(bl[nt], smem_u32(&sBlo[row * LDS + kb + bkq]));
            }
#pragma unroll
            for (int mt = 0; mt < 2; mt++)
#pragma unroll
                for (int nt = 0; nt < 4; nt++) {
                    mma_bf16(acc[mt][nt], ah[mt], bh[nt]);
                    mma_bf16(acc[mt][nt], ah[mt], bl[nt]);
                    mma_bf16(acc[mt][nt], al[mt], bh[nt]);
                }
        }
        __syncthreads();
    }

    // ---- epilogue ----
    const int g = lane >> 2;
    const int t = lane & 3;
#pragma unroll
    for (int mt = 0; mt < 2; mt++) {
        const int row0 = m0 + warp_m * 32 + mt * 16 + g;
#pragma unroll
        for (int nt = 0; nt < 4; nt++) {
            const int col = n0 + warp_n * 32 + nt * 8 + t * 2;
            float2 b2 = *(const float2*)(bias + col);
            float2 o0, o1;
            o0.x = acc[mt][nt][0] + b2.x;
            o0.y = acc[mt][nt][1] + b2.y;
            o1.x = acc[mt][nt][2] + b2.x;
            o1.y = acc[mt][nt][3] + b2.y;
            *(float2*)(C + (size_t)row0 * GN + col)       = o0;
            *(float2*)(C + (size_t)(row0 + 8) * GN + col) = o1;
        }
    }
}

// ---------------------------------------------------------------------------
// Flash attention (fp32, causal) — unchanged.
// ---------------------------------------------------------------------------
#define FA_BM 128
#define FA_BN 32

__global__ __launch_bounds__(128) void flash_attn(
    const float* __restrict__ Q, const float* __restrict__ K,
    const float* __restrict__ V, float* __restrict__ O)
{
    __shared__ float Ks[FA_BN][DEPTH];
    __shared__ float Vs[FA_BN][DEPTH];

    const int tid = threadIdx.x;
    const int bh  = blockIdx.y;
    const int b   = bh >> 4;
    const int h   = bh & 15;
    const int nqt = SEQ / FA_BM;
    const int q0  = (nqt - 1 - (int)blockIdx.x) * FA_BM;
    const int srow = q0 + tid;

    const float* qptr = Q + (size_t)(b * SEQ + srow) * D_MODEL + h * DEPTH;
    float4 qr[16];
#pragma unroll
    for (int i = 0; i < 16; i++) qr[i] = *(const float4*)(qptr + i * 4);

    float4 acc[16];
#pragma unroll
    for (int i = 0; i < 16; i++) acc[i] = make_float4(0.f, 0.f, 0.f, 0.f);
    float mrun = -1e30f, lrun = 0.f;

    const float scale = 0.125f;
    const int ntiles = q0 / FA_BN + FA_BM / FA_BN;

    for (int t = 0; t < ntiles; t++) {
        const int k0 = t * FA_BN;
#pragma unroll
        for (int i = 0; i < 4; i++) {
            int idx = tid + i * 128;
            int row = idx >> 4;
            int c4  = idx & 15;
            size_t goff = (size_t)(b * SEQ + k0 + row) * D_MODEL + h * DEPTH + c4 * 4;
            *(float4*)(&Ks[row][c4 * 4]) = *(const float4*)(K + goff);
            *(float4*)(&Vs[row][c4 * 4]) = *(const float4*)(V + goff);
        }
        __syncthreads();

        float s[FA_BN];
        float tmax = -1e30f;
#pragma unroll
        for (int j = 0; j < FA_BN; j++) {
            float s0 = 0.f, s1 = 0.f, s2 = 0.f, s3 = 0.f;
#pragma unroll
            for (int d4 = 0; d4 < 16; d4++) {
                float4 kv = *(const float4*)(&Ks[j][d4 * 4]);
                s0 = fmaf(qr[d4].x, kv.x, s0);
                s1 = fmaf(qr[d4].y, kv.y, s1);
                s2 = fmaf(qr[d4].z, kv.z, s2);
                s3 = fmaf(qr[d4].w, kv.w, s3);
            }
            float sj = ((s0 + s1) + (s2 + s3)) * scale;
            if (k0 + j > srow) sj = -1e30f;
            s[j] = sj;
            tmax = fmaxf(tmax, sj);
        }

        const float mnew = fmaxf(mrun, tmax);
        const float corr = __expf(mrun - mnew);
        lrun *= corr;
#pragma unroll
        for (int i = 0; i < 16; i++) {
            acc[i].x *= corr; acc[i].y *= corr;
            acc[i].z *= corr; acc[i].w *= corr;
        }

#pragma unroll
        for (int j = 0; j < FA_BN; j++) {
            float p = __expf(s[j] - mnew);
            lrun += p;
#pragma unroll
            for (int d4 = 0; d4 < 16; d4++) {
                float4 vv = *(const float4*)(&Vs[j][d4 * 4]);
                acc[d4].x = fmaf(p, vv.x, acc[d4].x);
                acc[d4].y = fmaf(p, vv.y, acc[d4].y);
                acc[d4].z = fmaf(p, vv.z, acc[d4].z);
                acc[d4].w = fmaf(p, vv.w, acc[d4].w);
            }
        }
        mrun = mnew;
        __syncthreads();
    }

    const float inv = 1.f / lrun;
    float* optr = O + (size_t)(b * SEQ + srow) * D_MODEL + h * DEPTH;
#pragma unroll
    for (int i = 0; i < 16; i++) {
        float4 o;
        o.x = acc[i].x * inv; o.y = acc[i].y * inv;
        o.z = acc[i].z * inv; o.w = acc[i].w * inv;
        *(float4*)(optr + i * 4) = o;
    }
}

// ---------------------------------------------------------------------------
// Launch: 0:v 1:k 2:q 3:mask 4:wq_w 5:wq_b 6:wk_w 7:wk_b 8:wv_w 9:wv_b
//         10:dense_w 11:dense_b
// ---------------------------------------------------------------------------
extern "C" void kernel_launch(void* const* d_in, const int* in_sizes, int n_in,
                              void* d_out, int out_size)
{
    const float* v       = (const float*)d_in[0];
    const float* k       = (const float*)d_in[1];
    const float* q       = (const float*)d_in[2];
    const float* wq_w    = (const float*)d_in[4];
    const float* wq_b    = (const float*)d_in[5];
    const float* wk_w    = (const float*)d_in[6];
    const float* wk_b    = (const float*)d_in[7];
    const float* wv_w    = (const float*)d_in[8];
    const float* wv_b    = (const float*)d_in[9];
    const float* dense_w = (const float*)d_in[10];
    const float* dense_b = (const float*)d_in[11];
    float* out = (float*)d_out;

    float *gq, *gk, *gv, *go;
    __nv_bfloat16 *ahi, *alo, *whi, *wlo;
    cudaGetSymbolAddress((void**)&gq, g_q);
    cudaGetSymbolAddress((void**)&gk, g_k);
    cudaGetSymbolAddress((void**)&gv, g_v);
    cudaGetSymbolAddress((void**)&go, g_o);
    cudaGetSymbolAddress((void**)&ahi, s_ahi);
    cudaGetSymbolAddress((void**)&alo, s_alo);
    cudaGetSymbolAddress((void**)&whi, s_whi);
    cudaGetSymbolAddress((void**)&wlo, s_wlo);

    const int nact4 = NROWS * D_MODEL / 4;
    const int nw4   = D_MODEL * D_MODEL / 4;
    dim3 ggrid(GN / 64, NROWS / 128);   // (16, 32)

    split_bf16<<<nact4 / 256, 256>>>(q, ahi, alo, nact4);
    split_bf16<<<nw4 / 256, 256>>>(wq_w, whi, wlo, nw4);
    gemm_mma_split<<<ggrid, 256>>>(ahi, alo, whi, wlo, wq_b, gq);

    split_bf16<<<nact4 / 256, 256>>>(k, ahi, alo, nact4);
    split_bf16<<<nw4 / 256, 256>>>(wk_w, whi, wlo, nw4);
    gemm_mma_split<<<ggrid, 256>>>(ahi, alo, whi, wlo, wk_b, gk);

    split_bf16<<<nact4 / 256, 256>>>(v, ahi, alo, nact4);
    split_bf16<<<nw4 / 256, 256>>>(wv_w, whi, wlo, nw4);
    gemm_mma_split<<<ggrid, 256>>>(ahi, alo, whi, wlo, wv_b, gv);

    dim3 fa_grid(SEQ / FA_BM, BATCH * NHEADS);
    flash_attn<<<fa_grid, 128>>>(gq, gk, gv, go);

    split_bf16<<<nact4 / 256, 256>>>(go, ahi, alo, nact4);
    split_bf16<<<nw4 / 256, 256>>>(dense_w, whi, wlo, nw4);
    gemm_mma_split<<<ggrid, 256>>>(ahi, alo, whi, wlo, dense_b, out);
}